// round 9
// baseline (speedup 1.0000x reference)
#include <cuda_runtime.h>

// DynamicConv2d: B=64, C=8, H=W=256, OUT_C=8, K=3, pad=1.
// R8: R7's och-pair f32x2 inner loop (3 LDS.32 + 3 splat-MOV + 18 FFMA2 per
//     (c,t)) + cp.async CHANNEL PIPELINE: per-channel double-buffered smem,
//     prefetch channel c+2 while computing channel c. Zero-fill borders via
//     cp.async src-size predication. Static smem ~13.5KB, 3 CTAs/SM.

typedef unsigned long long u64;

#define TY 8                     // output rows per tile
#define TX 128                   // output cols per tile
#define CB_STRIDE 136            // per-channel row stride (floats); col g at g+4
#define CB_ROWS (TY + 2)         // 10
#define CB_SIZE (CB_ROWS * CB_STRIDE)   // 1360 floats

// Packed weight scratch: [b][c*9+kk][o], o fastest => och pairs are 8-byte
// aligned LDS.64 after copy to smem.
__device__ __align__(16) float g_wpack[64 * 72 * 8];

__global__ void gen_weights_kernel(const float* __restrict__ dw,
                                   const float* __restrict__ Wg,
                                   const float* __restrict__ bg) {
    int b = blockIdx.x;
    int t = threadIdx.x;          // 0..575
    int j = t >> 3;               // c*9 + kk
    int o = t & 7;                // output channel (torch .view quirk)
    const float* dwp = dw + (b * 8 + o) * 8;
    const float* wgp = Wg + j * 8;
    float v = bg[j];
#pragma unroll
    for (int i = 0; i < 8; i++) v = fmaf(dwp[i], wgp[i], v);
    g_wpack[(b * 72 + j) * 8 + o] = v;
}

__device__ __forceinline__ void cp16(unsigned dst, const void* src, bool pred) {
    int sz = pred ? 16 : 0;
    asm volatile("cp.async.cg.shared.global [%0], [%1], 16, %2;"
                 :: "r"(dst), "l"(src), "r"(sz) : "memory");
}
__device__ __forceinline__ void cp4(unsigned dst, const void* src, bool pred) {
    int sz = pred ? 4 : 0;
    asm volatile("cp.async.ca.shared.global [%0], [%1], 4, %2;"
                 :: "r"(dst), "l"(src), "r"(sz) : "memory");
}
#define CP_COMMIT() asm volatile("cp.async.commit_group;" ::: "memory")

__global__ __launch_bounds__(256, 3)
void conv_kernel(const float* __restrict__ x, float* __restrict__ out) {
    __shared__ __align__(16) float sw[576];                 // packed weights
    __shared__ __align__(16) float buf[2][CB_SIZE + 8];     // channel double-buffer

    int bi = blockIdx.x;
    int b  = bi >> 6;              // batch
    int y0 = ((bi >> 1) & 31) * TY;
    int x0 = (bi & 1) * TX;
    int tx   = threadIdx.x;        // column within tile 0..127
    int half = threadIdx.y;        // och half: 0 -> och 0..3, 1 -> och 4..7
    int tid  = tx + (half << 7);   // 0..255

    const float* xb = x + (size_t)b * (8 * 65536);
    unsigned sw_s = (unsigned)__cvta_generic_to_shared(sw);
    unsigned bs_s[2];
    bs_s[0] = (unsigned)__cvta_generic_to_shared(&buf[0][0]);
    bs_s[1] = (unsigned)__cvta_generic_to_shared(&buf[1][0]);

    // --- channel loader: interior 10x32 quads via cp16, halo cols via cp4 ---
    auto load_ch = [&](int c, unsigned bs) {
#pragma unroll
        for (int i0 = 0; i0 < 320; i0 += 256) {
            int i = i0 + tid;
            if (i < 320) {
                int row = i >> 5, q = i & 31;
                int gy = y0 - 1 + row;
                cp16(bs + (row * CB_STRIDE + 4 * q + 4) * 4,
                     xb + c * 65536 + gy * 256 + x0 + 4 * q,
                     (unsigned)gy < 256u);
            }
        }
        if (tid < 20) {
            int side = tid >= 10;
            int r = side ? tid - 10 : tid;
            int gy = y0 - 1 + r;
            int gx = side ? (x0 + 128) : (x0 - 1);
            cp4(bs + (r * CB_STRIDE + (side ? 132 : 3)) * 4,
                xb + c * 65536 + gy * 256 + gx,
                ((unsigned)gy < 256u) && ((unsigned)gx < 256u));
        }
    };

    // --- prologue: weights + ch0 (group 0), ch1 (group 1) ---
    if (tid < 144)
        cp16(sw_s + tid * 16, g_wpack + b * 576 + tid * 4, true);
    load_ch(0, bs_s[0]);
    CP_COMMIT();
    load_ch(1, bs_s[1]);
    CP_COMMIT();

    u64 acc[TY][2];
#pragma unroll
    for (int r = 0; r < TY; r++) { acc[r][0] = 0ull; acc[r][1] = 0ull; }

    const u64* swq = (const u64*)sw;

#pragma unroll 1
    for (int c = 0; c < 8; c++) {
        if (c < 7) asm volatile("cp.async.wait_group 1;" ::: "memory");
        else       asm volatile("cp.async.wait_group 0;" ::: "memory");
        __syncthreads();            // channel c data visible to all threads

        // 18 natural weight pairs (broadcast LDS.64)
        u64 w[9][2];
#pragma unroll
        for (int kk = 0; kk < 9; kk++) {
#pragma unroll
            for (int p = 0; p < 2; p++)
                w[kk][p] = swq[(c * 9 + kk) * 4 + half * 2 + p];
        }
        const float* sc = buf[c & 1] + tx;
#pragma unroll
        for (int t = 0; t < CB_ROWS; t++) {
            float v0 = sc[t * CB_STRIDE + 3];   // col cx-1
            float v1 = sc[t * CB_STRIDE + 4];   // col cx
            float v2 = sc[t * CB_STRIDE + 5];   // col cx+1
            u64 d0, d1, d2;                     // (v,v) splats: 1 MOV each
            asm("mov.b64 %0, {%1, %1};" : "=l"(d0) : "f"(v0));
            asm("mov.b64 %0, {%1, %1};" : "=l"(d1) : "f"(v1));
            asm("mov.b64 %0, {%1, %1};" : "=l"(d2) : "f"(v2));
#pragma unroll
            for (int kh = 0; kh < 3; kh++) {
                int r = t - kh;                 // output row this tap feeds
                if (r >= 0 && r < TY) {
#pragma unroll
                    for (int p = 0; p < 2; p++) {
                        asm("fma.rn.f32x2 %0, %1, %2, %0;"
                            : "+l"(acc[r][p]) : "l"(d0), "l"(w[kh * 3 + 0][p]));
                        asm("fma.rn.f32x2 %0, %1, %2, %0;"
                            : "+l"(acc[r][p]) : "l"(d1), "l"(w[kh * 3 + 1][p]));
                        asm("fma.rn.f32x2 %0, %1, %2, %0;"
                            : "+l"(acc[r][p]) : "l"(d2), "l"(w[kh * 3 + 2][p]));
                    }
                }
            }
        }
        __syncthreads();            // all warps done with buf[c&1]
        if (c < 6) {                // prefetch channel c+2 into freed buffer
            load_ch(c + 2, bs_s[c & 1]);
            CP_COMMIT();
        }
    }

    // --- write out: acc[r][p] = (och 2q, och 2q+1), scalar STG each ---
    float* ob = out + (size_t)b * (8 * 65536) + x0;
#pragma unroll
    for (int r = 0; r < TY; r++) {
#pragma unroll
        for (int p = 0; p < 2; p++) {
            int q = half * 2 + p;
            unsigned lo, hi;
            asm("mov.b64 {%0, %1}, %2;" : "=r"(lo), "=r"(hi) : "l"(acc[r][p]));
            ob[(2 * q + 0) * 65536 + (y0 + r) * 256 + tx] = __uint_as_float(lo);
            ob[(2 * q + 1) * 65536 + (y0 + r) * 256 + tx] = __uint_as_float(hi);
        }
    }
}

extern "C" void kernel_launch(void* const* d_in, const int* in_sizes, int n_in,
                              void* d_out, int out_size) {
    const float* x  = (const float*)d_in[0];
    const float* dw = (const float*)d_in[1];
    const float* Wg = (const float*)d_in[2];
    const float* bg = (const float*)d_in[3];
    float* out = (float*)d_out;

    gen_weights_kernel<<<64, 576>>>(dw, Wg, bg);

    dim3 blk(128, 2, 1);
    conv_kernel<<<64 * 32 * 2, blk>>>(x, out);
}